// round 11
// baseline (speedup 1.0000x reference)
#include <cuda_runtime.h>
#include <math.h>

// MaskedLightAdaIN, two-kernel pipeline:
//   1) stats_kernel: 16384 blocks (one per 16KB segment of a plane).
//      Reads x (streaming) + mask f32 (L2-resident), writes 5-float partials
//      per segment to fixed slots, and (channel-0 blocks only) the bit-packed
//      mask for the apply pass. No atomics; fully deterministic.
//   2) apply_kernel: 16384 blocks, same shape. Each block redundantly combines
//      its plane's 16 partial slots in a FIXED order (identical result in every
//      block -> deterministic), computes scale/bias, then blends + streams out.
// x [16,64,256,256] f32, mask [16,1,256,256] f32.

#define NB      16
#define NBC     1024            // planes (B*C)
#define HW      65536
#define HW4     16384           // float4 per plane
#define SEG4    1024            // float4 per segment (16 KB)
#define NSEG    16              // segments per plane
#define PMW     2048            // packed-mask words per batch (HW/32)
#define EPSV    1e-8f

__device__ float    g_part[NBC * NSEG][5];   // s_all, q_all, s_fg, q_fg, n_fg
__device__ unsigned g_pm[NB][PMW];           // 1 bit / pixel

// ---------------------------------------------------------------------------
// Pass 1: per-segment partial sums (+ mask bit-packing from channel-0 blocks)
// ---------------------------------------------------------------------------
__global__ void __launch_bounds__(256) stats_kernel(const float* __restrict__ x,
                                                    const float* __restrict__ mask)
{
    __shared__ unsigned char nibs[SEG4];
    __shared__ float red[8][5];

    const int blk = blockIdx.x;         // 0..16383
    const int p   = blk >> 4;           // plane
    const int seg = blk & 15;           // segment
    const int b   = p >> 6;             // batch
    const int c   = p & 63;             // channel

    const float4* __restrict__ xp = reinterpret_cast<const float4*>(x)
                                  + (size_t)p * HW4 + (size_t)seg * SEG4;
    const float4* __restrict__ mp = reinterpret_cast<const float4*>(mask)
                                  + (size_t)b * HW4 + (size_t)seg * SEG4;

    // front-batch all 8 loads (4x + 4mask) before any arithmetic
    float4 xv[4], mv[4];
    #pragma unroll
    for (int k = 0; k < 4; k++) {
        const int i = threadIdx.x + (k << 8);
        xv[k] = __ldcs(&xp[i]);         // streaming: no reuse before apply
        mv[k] = mp[i];                  // cached: 64x reuse per batch via L2
    }

    float s_all = 0.f, q_all = 0.f, s_fg = 0.f, q_fg = 0.f;
    int   n_cnt = 0;

    #pragma unroll
    for (int k = 0; k < 4; k++) {
        const int i = threadIdx.x + (k << 8);
        unsigned m0 = (mv[k].x >= 0.5f), m1 = (mv[k].y >= 0.5f),
                 m2 = (mv[k].z >= 0.5f), m3 = (mv[k].w >= 0.5f);
        unsigned nib = m0 | (m1 << 1) | (m2 << 2) | (m3 << 3);
        nibs[i] = (unsigned char)nib;

        float x0 = xv[k].x, x1 = xv[k].y, x2 = xv[k].z, x3 = xv[k].w;
        float q0 = x0*x0, q1 = x1*x1, q2 = x2*x2, q3 = x3*x3;

        s_all += x0 + x1 + x2 + x3;
        q_all += q0 + q1 + q2 + q3;
        if (m0) { s_fg += x0; q_fg += q0; }
        if (m1) { s_fg += x1; q_fg += q1; }
        if (m2) { s_fg += x2; q_fg += q2; }
        if (m3) { s_fg += x3; q_fg += q3; }
        n_cnt += (int)(m0 + m1 + m2 + m3);
    }
    float n_fg = (float)n_cnt;

    // warp reduce (5 values)
    #pragma unroll
    for (int o = 16; o > 0; o >>= 1) {
        s_all += __shfl_xor_sync(0xffffffffu, s_all, o);
        q_all += __shfl_xor_sync(0xffffffffu, q_all, o);
        s_fg  += __shfl_xor_sync(0xffffffffu, s_fg,  o);
        q_fg  += __shfl_xor_sync(0xffffffffu, q_fg,  o);
        n_fg  += __shfl_xor_sync(0xffffffffu, n_fg,  o);
    }
    const int warp = threadIdx.x >> 5;
    const int lane = threadIdx.x & 31;
    if (lane == 0) {
        red[warp][0] = s_all; red[warp][1] = q_all;
        red[warp][2] = s_fg;  red[warp][3] = q_fg;
        red[warp][4] = n_fg;
    }
    __syncthreads();   // covers both red[] and nibs[]

    // channel-0 blocks also publish the packed mask for this segment
    if (c == 0 && threadIdx.x < 128) {
        unsigned bits = 0;
        #pragma unroll
        for (int j = 0; j < 8; j++)
            bits |= (unsigned)nibs[threadIdx.x * 8 + j] << (4 * j);
        g_pm[b][seg * 128 + threadIdx.x] = bits;
    }

    if (threadIdx.x < 32) {
        float v0 = (lane < 8) ? red[lane][0] : 0.f;
        float v1 = (lane < 8) ? red[lane][1] : 0.f;
        float v2 = (lane < 8) ? red[lane][2] : 0.f;
        float v3 = (lane < 8) ? red[lane][3] : 0.f;
        float v4 = (lane < 8) ? red[lane][4] : 0.f;
        #pragma unroll
        for (int o = 4; o > 0; o >>= 1) {
            v0 += __shfl_xor_sync(0xffffffffu, v0, o);
            v1 += __shfl_xor_sync(0xffffffffu, v1, o);
            v2 += __shfl_xor_sync(0xffffffffu, v2, o);
            v3 += __shfl_xor_sync(0xffffffffu, v3, o);
            v4 += __shfl_xor_sync(0xffffffffu, v4, o);
        }
        if (lane == 0) {
            float* gp = g_part[p * NSEG + seg];
            gp[0] = v0; gp[1] = v1; gp[2] = v2; gp[3] = v3; gp[4] = v4;
        }
    }
}

// ---------------------------------------------------------------------------
// Pass 2: apply. Each block combines its plane's 16 slots (fixed order ->
// deterministic, identical across the plane's 16 blocks), then blends.
// ---------------------------------------------------------------------------
__global__ void __launch_bounds__(256) apply_kernel(const float* __restrict__ x,
                                                    float* __restrict__ out)
{
    const int blk = blockIdx.x;         // 0..16383
    const int p   = blk >> 4;
    const int seg = blk & 15;
    const int b   = p >> 6;

    const size_t xoff = (size_t)p * HW4 + (size_t)seg * SEG4;
    const float4* __restrict__ xp = reinterpret_cast<const float4*>(x) + xoff;
    float4*       __restrict__ op = reinterpret_cast<float4*>(out)     + xoff;
    const unsigned* __restrict__ pm = &g_pm[b][0];
    const int fbase = seg * SEG4;

    // issue the big loads first so the finalize math hides under them
    float4 xv[4];
    unsigned nib[4];
    #pragma unroll
    for (int k = 0; k < 4; k++) {
        const int i = threadIdx.x + (k << 8);
        xv[k] = __ldcs(&xp[i]);
        const int f = fbase + i;
        nib[k] = (pm[f >> 3] >> ((f & 7) * 4)) & 0xFu;
    }

    // redundant per-block finalize (fixed order, deterministic)
    const float* __restrict__ gp = &g_part[p * NSEG][0];
    float t0 = 0.f, t1 = 0.f, t2 = 0.f, t3 = 0.f, nf = 0.f;
    #pragma unroll
    for (int s = 0; s < NSEG; s++) {
        t0 += gp[s*5 + 0];
        t1 += gp[s*5 + 1];
        t2 += gp[s*5 + 2];
        t3 += gp[s*5 + 3];
        nf += gp[s*5 + 4];
    }
    float nb  = (float)HW - nf;
    float s_b = t0 - t2, q_b = t1 - t3;

    float mu_f  = t2 / nf;
    float var_f = fmaxf(t3 - t2 * mu_f, 0.f) / (nf - 1.f);
    float sig_f = sqrtf(var_f);

    float mu_b  = s_b / nb;
    float var_b = fmaxf(q_b - s_b * mu_b, 0.f) / (nb - 1.f);
    float sig_b = sqrtf(var_b);

    const float scale = sig_f / (sig_b + EPSV);
    const float bias  = mu_f - mu_b * scale;

    #pragma unroll
    for (int k = 0; k < 4; k++) {
        const int i = threadIdx.x + (k << 8);
        float4 ov;
        ov.x = (nib[k] & 1u) ? xv[k].x : fmaf(xv[k].x, scale, bias);
        ov.y = (nib[k] & 2u) ? xv[k].y : fmaf(xv[k].y, scale, bias);
        ov.z = (nib[k] & 4u) ? xv[k].z : fmaf(xv[k].z, scale, bias);
        ov.w = (nib[k] & 8u) ? xv[k].w : fmaf(xv[k].w, scale, bias);
        __stcs(&op[i], ov);
    }
}

extern "C" void kernel_launch(void* const* d_in, const int* in_sizes, int n_in,
                              void* d_out, int out_size)
{
    const float* x    = (const float*)d_in[0];
    const float* mask = (const float*)d_in[1];
    float* out        = (float*)d_out;

    stats_kernel<<<NBC * NSEG, 256>>>(x, mask);
    apply_kernel<<<NBC * NSEG, 256>>>(x, out);
}

// round 12
// speedup vs baseline: 1.0803x; 1.0803x over previous
#include <cuda_runtime.h>
#include <math.h>

// MaskedLightAdaIN, four-launch pipeline with L2 carryover:
//   0) pack_kernel:     mask f32 -> 1 bit/pixel (128 KB)
//   1) stats_kernel:    per quarter-plane partials; x loaded with NORMAL
//                       caching so the ~120MB tail of x stays in L2
//   2) finalize_kernel: combine 4 slots/plane -> scale/bias (deterministic)
//   3) apply_kernel:    walks planes in REVERSE so it consumes the L2-resident
//                       tail first; __ldcs/__stcs keep consumed lines evict-first
// x [16,64,256,256] f32, mask [16,1,256,256] f32.

#define NB      16
#define NBC     1024            // planes (B*C)
#define HW      65536
#define HW4     16384           // float4 per plane
#define Q4      4096            // float4 per quarter plane
#define PMW     2048            // packed-mask words per batch (HW/32)
#define EPSV    1e-8f

__device__ unsigned g_pm[NB][PMW];    // 1 bit per pixel
__device__ float    g_part[NBC][4][5];
__device__ float2   g_sb[NBC];

// ---------------------------------------------------------------------------
// Pass 0: bit-pack the mask. One thread per uint32 word (32 pixels).
// ---------------------------------------------------------------------------
__global__ void __launch_bounds__(256) pack_kernel(const float* __restrict__ mask)
{
    const int w  = blockIdx.x * 256 + threadIdx.x;   // 0..32767
    const int b  = w >> 11;
    const int wi = w & (PMW - 1);

    const float4* __restrict__ mp = reinterpret_cast<const float4*>(mask)
                                  + (size_t)b * HW4 + wi * 8;
    unsigned bits = 0;
    #pragma unroll
    for (int k = 0; k < 8; k++) {
        float4 mv = __ldcs(&mp[k]);
        unsigned nib = (mv.x >= 0.5f) | ((mv.y >= 0.5f) << 1)
                     | ((mv.z >= 0.5f) << 2) | ((mv.w >= 0.5f) << 3);
        bits |= nib << (4 * k);
    }
    g_pm[b][wi] = bits;
}

// ---------------------------------------------------------------------------
// Pass 1: partial sums per quarter-plane. 256 threads x 16 float4.
// x loaded with default policy -> tail of x survives in L2 for the apply pass.
// ---------------------------------------------------------------------------
__global__ void __launch_bounds__(256) stats_kernel(const float* __restrict__ x)
{
    const int blk = blockIdx.x;         // 0..4095
    const int p   = blk >> 2;           // plane
    const int q   = blk & 3;            // quarter
    const int b   = p >> 6;             // batch

    const float4* __restrict__ xp = reinterpret_cast<const float4*>(x)
                                  + (size_t)p * HW4 + q * Q4;
    const unsigned* __restrict__ pm = &g_pm[b][0];
    const int fbase = q * Q4;

    float s_all = 0.f, q_all = 0.f, s_fg = 0.f, q_fg = 0.f;
    int   n_cnt = 0;

    #pragma unroll 4
    for (int k = 0; k < 16; k++) {
        const int i = threadIdx.x + (k << 8);
        float4 xv = xp[i];              // NORMAL load: keep in L2
        const int f = fbase + i;
        unsigned nib = (pm[f >> 3] >> ((f & 7) * 4)) & 0xFu;

        float x0 = xv.x, x1 = xv.y, x2 = xv.z, x3 = xv.w;
        float q0 = x0*x0, q1 = x1*x1, q2 = x2*x2, q3 = x3*x3;

        s_all += x0 + x1 + x2 + x3;
        q_all += q0 + q1 + q2 + q3;
        if (nib & 1u) { s_fg += x0; q_fg += q0; }
        if (nib & 2u) { s_fg += x1; q_fg += q1; }
        if (nib & 4u) { s_fg += x2; q_fg += q2; }
        if (nib & 8u) { s_fg += x3; q_fg += q3; }
        n_cnt += __popc(nib);
    }
    float n_fg = (float)n_cnt;

    #pragma unroll
    for (int o = 16; o > 0; o >>= 1) {
        s_all += __shfl_xor_sync(0xffffffffu, s_all, o);
        q_all += __shfl_xor_sync(0xffffffffu, q_all, o);
        s_fg  += __shfl_xor_sync(0xffffffffu, s_fg,  o);
        q_fg  += __shfl_xor_sync(0xffffffffu, q_fg,  o);
        n_fg  += __shfl_xor_sync(0xffffffffu, n_fg,  o);
    }

    __shared__ float red[8][5];
    const int warp = threadIdx.x >> 5;
    const int lane = threadIdx.x & 31;
    if (lane == 0) {
        red[warp][0] = s_all; red[warp][1] = q_all;
        red[warp][2] = s_fg;  red[warp][3] = q_fg;
        red[warp][4] = n_fg;
    }
    __syncthreads();

    if (threadIdx.x < 32) {
        float v0 = (lane < 8) ? red[lane][0] : 0.f;
        float v1 = (lane < 8) ? red[lane][1] : 0.f;
        float v2 = (lane < 8) ? red[lane][2] : 0.f;
        float v3 = (lane < 8) ? red[lane][3] : 0.f;
        float v4 = (lane < 8) ? red[lane][4] : 0.f;
        #pragma unroll
        for (int o = 4; o > 0; o >>= 1) {
            v0 += __shfl_xor_sync(0xffffffffu, v0, o);
            v1 += __shfl_xor_sync(0xffffffffu, v1, o);
            v2 += __shfl_xor_sync(0xffffffffu, v2, o);
            v3 += __shfl_xor_sync(0xffffffffu, v3, o);
            v4 += __shfl_xor_sync(0xffffffffu, v4, o);
        }
        if (lane == 0) {
            g_part[p][q][0] = v0;
            g_part[p][q][1] = v1;
            g_part[p][q][2] = v2;
            g_part[p][q][3] = v3;
            g_part[p][q][4] = v4;
        }
    }
}

// ---------------------------------------------------------------------------
// Pass 2: combine quarter slots (fixed order -> bit-deterministic)
// ---------------------------------------------------------------------------
__global__ void finalize_kernel()
{
    const int p = blockIdx.x * blockDim.x + threadIdx.x;
    if (p >= NBC) return;

    float t0 = 0.f, t1 = 0.f, t2 = 0.f, t3 = 0.f, nf = 0.f;
    #pragma unroll
    for (int s = 0; s < 4; s++) {
        t0 += g_part[p][s][0];
        t1 += g_part[p][s][1];
        t2 += g_part[p][s][2];
        t3 += g_part[p][s][3];
        nf += g_part[p][s][4];
    }
    float nb  = (float)HW - nf;
    float s_b = t0 - t2, q_b = t1 - t3;

    float mu_f  = t2 / nf;
    float var_f = fmaxf(t3 - t2 * mu_f, 0.f) / (nf - 1.f);
    float sig_f = sqrtf(var_f);

    float mu_b  = s_b / nb;
    float var_b = fmaxf(q_b - s_b * mu_b, 0.f) / (nb - 1.f);
    float sig_b = sqrtf(var_b);

    float scale = sig_f / (sig_b + EPSV);
    float bias  = mu_f - mu_b * scale;
    g_sb[p] = make_float2(scale, bias);
}

// ---------------------------------------------------------------------------
// Pass 3: elementwise apply, REVERSED block order so the first blocks consume
// the x lines that stats left resident in L2.
// ---------------------------------------------------------------------------
__global__ void __launch_bounds__(256) apply_kernel(const float* __restrict__ x,
                                                    float* __restrict__ out)
{
    const int blk = (16 * NBC - 1) - blockIdx.x;   // reverse: high addresses first
    const int p   = blk >> 4;           // plane
    const int seg = blk & 15;           // 1024-float4 segment
    const int b   = p >> 6;

    const size_t xoff = (size_t)p * HW4 + (size_t)seg * 1024;
    const float4* __restrict__ xp = reinterpret_cast<const float4*>(x) + xoff;
    float4*       __restrict__ op = reinterpret_cast<float4*>(out)     + xoff;
    const unsigned* __restrict__ pm = &g_pm[b][0];
    const int fbase = seg * 1024;

    const float2 sb = g_sb[p];
    const float scale = sb.x;
    const float bias  = sb.y;

    #pragma unroll
    for (int k = 0; k < 4; k++) {
        const int i = threadIdx.x + (k << 8);
        float4 xv = __ldcs(&xp[i]);     // hits L2 if resident; evict-first after
        const int f = fbase + i;
        unsigned nib = (pm[f >> 3] >> ((f & 7) * 4)) & 0xFu;

        float4 ov;
        ov.x = (nib & 1u) ? xv.x : fmaf(xv.x, scale, bias);
        ov.y = (nib & 2u) ? xv.y : fmaf(xv.y, scale, bias);
        ov.z = (nib & 4u) ? xv.z : fmaf(xv.z, scale, bias);
        ov.w = (nib & 8u) ? xv.w : fmaf(xv.w, scale, bias);

        __stcs(&op[i], ov);             // streaming write: evict-first
    }
}

extern "C" void kernel_launch(void* const* d_in, const int* in_sizes, int n_in,
                              void* d_out, int out_size)
{
    const float* x    = (const float*)d_in[0];
    const float* mask = (const float*)d_in[1];
    float* out        = (float*)d_out;

    pack_kernel<<<128, 256>>>(mask);
    stats_kernel<<<4 * NBC, 256>>>(x);
    finalize_kernel<<<4, 256>>>();
    apply_kernel<<<16 * NBC, 256>>>(x, out);
}

// round 13
// speedup vs baseline: 1.1207x; 1.0374x over previous
#include <cuda_runtime.h>
#include <math.h>

// MaskedLightAdaIN, four-launch pipeline:
//   0) pack_kernel:     mask f32 -> 1 bit/pixel (128 KB)
//   1) stats_kernel:    per quarter-plane partials; 8-deep front-batched loads
//   2) finalize_kernel: combine 4 slots/plane -> scale/bias (deterministic)
//   3) apply_kernel:    reversed walk, streaming loads/stores (R12 proven)
// x [16,64,256,256] f32, mask [16,1,256,256] f32.

#define NB      16
#define NBC     1024            // planes (B*C)
#define HW      65536
#define HW4     16384           // float4 per plane
#define Q4      4096            // float4 per quarter plane
#define PMW     2048            // packed-mask words per batch (HW/32)
#define EPSV    1e-8f

__device__ unsigned g_pm[NB][PMW];    // 1 bit per pixel
__device__ float    g_part[NBC][4][5];
__device__ float2   g_sb[NBC];

// ---------------------------------------------------------------------------
// Pass 0: bit-pack the mask. One thread per uint32 word (32 pixels).
// ---------------------------------------------------------------------------
__global__ void __launch_bounds__(256) pack_kernel(const float* __restrict__ mask)
{
    const int w  = blockIdx.x * 256 + threadIdx.x;   // 0..32767
    const int b  = w >> 11;
    const int wi = w & (PMW - 1);

    const float4* __restrict__ mp = reinterpret_cast<const float4*>(mask)
                                  + (size_t)b * HW4 + wi * 8;
    unsigned bits = 0;
    #pragma unroll
    for (int k = 0; k < 8; k++) {
        float4 mv = __ldcs(&mp[k]);
        unsigned nib = (mv.x >= 0.5f) | ((mv.y >= 0.5f) << 1)
                     | ((mv.z >= 0.5f) << 2) | ((mv.w >= 0.5f) << 3);
        bits |= nib << (4 * k);
    }
    g_pm[b][wi] = bits;
}

// ---------------------------------------------------------------------------
// Pass 1: partial sums per quarter-plane. 256 threads x 16 float4 each,
// processed as 2 rounds of 8 front-batched LDG.128 (high MLP before math).
// ---------------------------------------------------------------------------
__global__ void __launch_bounds__(256) stats_kernel(const float* __restrict__ x)
{
    const int blk = blockIdx.x;         // 0..4095
    const int p   = blk >> 2;           // plane
    const int q   = blk & 3;            // quarter
    const int b   = p >> 6;             // batch

    const float4* __restrict__ xp = reinterpret_cast<const float4*>(x)
                                  + (size_t)p * HW4 + q * Q4;
    const unsigned* __restrict__ pm = &g_pm[b][0];
    const int fbase = q * Q4;
    const int shift = (threadIdx.x & 7) * 4;   // nibble position: thread-invariant

    float s_all = 0.f, q_all = 0.f, s_fg = 0.f, q_fg = 0.f;
    int   n_cnt = 0;

    #pragma unroll
    for (int half = 0; half < 2; half++) {
        float4   r[8];
        unsigned w[8];
        // front-batch: 8 x-loads + 8 bit-word loads, no math in between
        #pragma unroll
        for (int k = 0; k < 8; k++) {
            const int i = threadIdx.x + ((half * 8 + k) << 8);
            r[k] = __ldcs(&xp[i]);
            w[k] = pm[(fbase + i) >> 3];
        }
        #pragma unroll
        for (int k = 0; k < 8; k++) {
            unsigned nib = (w[k] >> shift) & 0xFu;
            float x0 = r[k].x, x1 = r[k].y, x2 = r[k].z, x3 = r[k].w;
            float q0 = x0*x0, q1 = x1*x1, q2 = x2*x2, q3 = x3*x3;

            s_all += x0 + x1 + x2 + x3;
            q_all += q0 + q1 + q2 + q3;
            if (nib & 1u) { s_fg += x0; q_fg += q0; }
            if (nib & 2u) { s_fg += x1; q_fg += q1; }
            if (nib & 4u) { s_fg += x2; q_fg += q2; }
            if (nib & 8u) { s_fg += x3; q_fg += q3; }
            n_cnt += __popc(nib);
        }
    }
    float n_fg = (float)n_cnt;

    #pragma unroll
    for (int o = 16; o > 0; o >>= 1) {
        s_all += __shfl_xor_sync(0xffffffffu, s_all, o);
        q_all += __shfl_xor_sync(0xffffffffu, q_all, o);
        s_fg  += __shfl_xor_sync(0xffffffffu, s_fg,  o);
        q_fg  += __shfl_xor_sync(0xffffffffu, q_fg,  o);
        n_fg  += __shfl_xor_sync(0xffffffffu, n_fg,  o);
    }

    __shared__ float red[8][5];
    const int warp = threadIdx.x >> 5;
    const int lane = threadIdx.x & 31;
    if (lane == 0) {
        red[warp][0] = s_all; red[warp][1] = q_all;
        red[warp][2] = s_fg;  red[warp][3] = q_fg;
        red[warp][4] = n_fg;
    }
    __syncthreads();

    if (threadIdx.x < 32) {
        float v0 = (lane < 8) ? red[lane][0] : 0.f;
        float v1 = (lane < 8) ? red[lane][1] : 0.f;
        float v2 = (lane < 8) ? red[lane][2] : 0.f;
        float v3 = (lane < 8) ? red[lane][3] : 0.f;
        float v4 = (lane < 8) ? red[lane][4] : 0.f;
        #pragma unroll
        for (int o = 4; o > 0; o >>= 1) {
            v0 += __shfl_xor_sync(0xffffffffu, v0, o);
            v1 += __shfl_xor_sync(0xffffffffu, v1, o);
            v2 += __shfl_xor_sync(0xffffffffu, v2, o);
            v3 += __shfl_xor_sync(0xffffffffu, v3, o);
            v4 += __shfl_xor_sync(0xffffffffu, v4, o);
        }
        if (lane == 0) {
            g_part[p][q][0] = v0;
            g_part[p][q][1] = v1;
            g_part[p][q][2] = v2;
            g_part[p][q][3] = v3;
            g_part[p][q][4] = v4;
        }
    }
}

// ---------------------------------------------------------------------------
// Pass 2: combine quarter slots (fixed order -> bit-deterministic)
// ---------------------------------------------------------------------------
__global__ void finalize_kernel()
{
    const int p = blockIdx.x * blockDim.x + threadIdx.x;
    if (p >= NBC) return;

    float t0 = 0.f, t1 = 0.f, t2 = 0.f, t3 = 0.f, nf = 0.f;
    #pragma unroll
    for (int s = 0; s < 4; s++) {
        t0 += g_part[p][s][0];
        t1 += g_part[p][s][1];
        t2 += g_part[p][s][2];
        t3 += g_part[p][s][3];
        nf += g_part[p][s][4];
    }
    float nb  = (float)HW - nf;
    float s_b = t0 - t2, q_b = t1 - t3;

    float mu_f  = t2 / nf;
    float var_f = fmaxf(t3 - t2 * mu_f, 0.f) / (nf - 1.f);
    float sig_f = sqrtf(var_f);

    float mu_b  = s_b / nb;
    float var_b = fmaxf(q_b - s_b * mu_b, 0.f) / (nb - 1.f);
    float sig_b = sqrtf(var_b);

    float scale = sig_f / (sig_b + EPSV);
    float bias  = mu_f - mu_b * scale;
    g_sb[p] = make_float2(scale, bias);
}

// ---------------------------------------------------------------------------
// Pass 3: elementwise apply, reversed block order (L2 tail reuse), streaming.
// ---------------------------------------------------------------------------
__global__ void __launch_bounds__(256) apply_kernel(const float* __restrict__ x,
                                                    float* __restrict__ out)
{
    const int blk = (16 * NBC - 1) - blockIdx.x;   // reverse: high addresses first
    const int p   = blk >> 4;           // plane
    const int seg = blk & 15;           // 1024-float4 segment
    const int b   = p >> 6;

    const size_t xoff = (size_t)p * HW4 + (size_t)seg * 1024;
    const float4* __restrict__ xp = reinterpret_cast<const float4*>(x) + xoff;
    float4*       __restrict__ op = reinterpret_cast<float4*>(out)     + xoff;
    const unsigned* __restrict__ pm = &g_pm[b][0];
    const int fbase = seg * 1024;

    const float2 sb = g_sb[p];
    const float scale = sb.x;
    const float bias  = sb.y;

    #pragma unroll
    for (int k = 0; k < 4; k++) {
        const int i = threadIdx.x + (k << 8);
        float4 xv = __ldcs(&xp[i]);
        const int f = fbase + i;
        unsigned nib = (pm[f >> 3] >> ((f & 7) * 4)) & 0xFu;

        float4 ov;
        ov.x = (nib & 1u) ? xv.x : fmaf(xv.x, scale, bias);
        ov.y = (nib & 2u) ? xv.y : fmaf(xv.y, scale, bias);
        ov.z = (nib & 4u) ? xv.z : fmaf(xv.z, scale, bias);
        ov.w = (nib & 8u) ? xv.w : fmaf(xv.w, scale, bias);

        __stcs(&op[i], ov);
    }
}

extern "C" void kernel_launch(void* const* d_in, const int* in_sizes, int n_in,
                              void* d_out, int out_size)
{
    const float* x    = (const float*)d_in[0];
    const float* mask = (const float*)d_in[1];
    float* out        = (float*)d_out;

    pack_kernel<<<128, 256>>>(mask);
    stats_kernel<<<4 * NBC, 256>>>(x);
    finalize_kernel<<<4, 256>>>();
    apply_kernel<<<16 * NBC, 256>>>(x, out);
}

// round 14
// speedup vs baseline: 1.1642x; 1.0389x over previous
#include <cuda_runtime.h>
#include <math.h>

// MaskedLightAdaIN, four-launch PDL pipeline:
//   0) pack_kernel:     mask f32 -> 1 bit/pixel (128 KB)
//   1) stats_kernel:    per quarter-plane partials, 8-deep front-batched x
//                       loads BEFORE griddepsync (overlap with pack tail)
//   2) finalize_kernel: combine 4 slots/plane -> scale/bias (deterministic)
//   3) apply_kernel:    front-batched x loads before griddepsync (overlap with
//                       stats/finalize tails), then blend + streaming stores
// All dependent launches use ProgrammaticStreamSerialization; every read of
// predecessor-written data happens after cudaGridDependencySynchronize().

#define NB      16
#define NBC     1024            // planes (B*C)
#define HW      65536
#define HW4     16384           // float4 per plane
#define Q4      4096            // float4 per quarter plane
#define PMW     2048            // packed-mask words per batch (HW/32)
#define EPSV    1e-8f

__device__ unsigned g_pm[NB][PMW];    // 1 bit per pixel
__device__ float    g_part[NBC][4][5];
__device__ float2   g_sb[NBC];

// ---------------------------------------------------------------------------
// Pass 0: bit-pack the mask. One thread per uint32 word (32 pixels).
// ---------------------------------------------------------------------------
__global__ void __launch_bounds__(256) pack_kernel(const float* __restrict__ mask)
{
    const int w  = blockIdx.x * 256 + threadIdx.x;   // 0..32767
    const int b  = w >> 11;
    const int wi = w & (PMW - 1);

    const float4* __restrict__ mp = reinterpret_cast<const float4*>(mask)
                                  + (size_t)b * HW4 + wi * 8;
    unsigned bits = 0;
    #pragma unroll
    for (int k = 0; k < 8; k++) {
        float4 mv = __ldcs(&mp[k]);
        unsigned nib = (mv.x >= 0.5f) | ((mv.y >= 0.5f) << 1)
                     | ((mv.z >= 0.5f) << 2) | ((mv.w >= 0.5f) << 3);
        bits |= nib << (4 * k);
    }
    g_pm[b][wi] = bits;
}

// ---------------------------------------------------------------------------
// Pass 1: partial sums per quarter-plane. 512 threads x 8 float4, all loads
// of x front-batched BEFORE the dependency sync (x doesn't depend on pack).
// ---------------------------------------------------------------------------
__global__ void __launch_bounds__(512) stats_kernel(const float* __restrict__ x)
{
    const int blk = blockIdx.x;         // 0..4095
    const int p   = blk >> 2;           // plane
    const int q   = blk & 3;            // quarter
    const int b   = p >> 6;             // batch

    const float4* __restrict__ xp = reinterpret_cast<const float4*>(x)
                                  + (size_t)p * HW4 + q * Q4;
    const unsigned* __restrict__ pm = &g_pm[b][0];
    const int fbase = q * Q4;
    const int shift = (threadIdx.x & 7) * 4;   // stride 512 == 0 mod 8

    // front-batch: 8 independent LDG.128 of x
    float4 r[8];
    #pragma unroll
    for (int k = 0; k < 8; k++)
        r[k] = __ldcs(&xp[threadIdx.x + (k << 9)]);

#if __CUDA_ARCH__ >= 900
    cudaGridDependencySynchronize();    // pack's g_pm now visible
#endif

    unsigned w[8];
    #pragma unroll
    for (int k = 0; k < 8; k++)
        w[k] = pm[(fbase + threadIdx.x + (k << 9)) >> 3];

    float s_all = 0.f, q_all = 0.f, s_fg = 0.f, q_fg = 0.f;
    int   n_cnt = 0;

    #pragma unroll
    for (int k = 0; k < 8; k++) {
        unsigned nib = (w[k] >> shift) & 0xFu;
        float x0 = r[k].x, x1 = r[k].y, x2 = r[k].z, x3 = r[k].w;
        float q0 = x0*x0, q1 = x1*x1, q2 = x2*x2, q3 = x3*x3;

        s_all += x0 + x1 + x2 + x3;
        q_all += q0 + q1 + q2 + q3;
        if (nib & 1u) { s_fg += x0; q_fg += q0; }
        if (nib & 2u) { s_fg += x1; q_fg += q1; }
        if (nib & 4u) { s_fg += x2; q_fg += q2; }
        if (nib & 8u) { s_fg += x3; q_fg += q3; }
        n_cnt += __popc(nib);
    }
    float n_fg = (float)n_cnt;

    #pragma unroll
    for (int o = 16; o > 0; o >>= 1) {
        s_all += __shfl_xor_sync(0xffffffffu, s_all, o);
        q_all += __shfl_xor_sync(0xffffffffu, q_all, o);
        s_fg  += __shfl_xor_sync(0xffffffffu, s_fg,  o);
        q_fg  += __shfl_xor_sync(0xffffffffu, q_fg,  o);
        n_fg  += __shfl_xor_sync(0xffffffffu, n_fg,  o);
    }

    __shared__ float red[16][5];
    const int warp = threadIdx.x >> 5;
    const int lane = threadIdx.x & 31;
    if (lane == 0) {
        red[warp][0] = s_all; red[warp][1] = q_all;
        red[warp][2] = s_fg;  red[warp][3] = q_fg;
        red[warp][4] = n_fg;
    }
    __syncthreads();

    if (threadIdx.x < 32) {
        float v0 = (lane < 16) ? red[lane][0] : 0.f;
        float v1 = (lane < 16) ? red[lane][1] : 0.f;
        float v2 = (lane < 16) ? red[lane][2] : 0.f;
        float v3 = (lane < 16) ? red[lane][3] : 0.f;
        float v4 = (lane < 16) ? red[lane][4] : 0.f;
        #pragma unroll
        for (int o = 8; o > 0; o >>= 1) {
            v0 += __shfl_xor_sync(0xffffffffu, v0, o);
            v1 += __shfl_xor_sync(0xffffffffu, v1, o);
            v2 += __shfl_xor_sync(0xffffffffu, v2, o);
            v3 += __shfl_xor_sync(0xffffffffu, v3, o);
            v4 += __shfl_xor_sync(0xffffffffu, v4, o);
        }
        if (lane == 0) {
            g_part[p][q][0] = v0;
            g_part[p][q][1] = v1;
            g_part[p][q][2] = v2;
            g_part[p][q][3] = v3;
            g_part[p][q][4] = v4;
        }
    }
}

// ---------------------------------------------------------------------------
// Pass 2: combine quarter slots (fixed order -> bit-deterministic)
// ---------------------------------------------------------------------------
__global__ void finalize_kernel()
{
#if __CUDA_ARCH__ >= 900
    cudaGridDependencySynchronize();    // stats' g_part now visible
#endif
    const int p = blockIdx.x * blockDim.x + threadIdx.x;
    if (p >= NBC) return;

    float t0 = 0.f, t1 = 0.f, t2 = 0.f, t3 = 0.f, nf = 0.f;
    #pragma unroll
    for (int s = 0; s < 4; s++) {
        t0 += g_part[p][s][0];
        t1 += g_part[p][s][1];
        t2 += g_part[p][s][2];
        t3 += g_part[p][s][3];
        nf += g_part[p][s][4];
    }
    float nb  = (float)HW - nf;
    float s_b = t0 - t2, q_b = t1 - t3;

    float mu_f  = t2 / nf;
    float var_f = fmaxf(t3 - t2 * mu_f, 0.f) / (nf - 1.f);
    float sig_f = sqrtf(var_f);

    float mu_b  = s_b / nb;
    float var_b = fmaxf(q_b - s_b * mu_b, 0.f) / (nb - 1.f);
    float sig_b = sqrtf(var_b);

    float scale = sig_f / (sig_b + EPSV);
    float bias  = mu_f - mu_b * scale;
    g_sb[p] = make_float2(scale, bias);
}

// ---------------------------------------------------------------------------
// Pass 3: apply. x loads front-batched BEFORE the dependency sync; everything
// written by predecessors (g_pm, g_sb) is read after it. Reversed block order
// keeps the weak L2-tail reuse from R12.
// ---------------------------------------------------------------------------
__global__ void __launch_bounds__(256) apply_kernel(const float* __restrict__ x,
                                                    float* __restrict__ out)
{
    const int blk = (16 * NBC - 1) - blockIdx.x;
    const int p   = blk >> 4;           // plane
    const int seg = blk & 15;           // 1024-float4 segment
    const int b   = p >> 6;

    const size_t xoff = (size_t)p * HW4 + (size_t)seg * 1024;
    const float4* __restrict__ xp = reinterpret_cast<const float4*>(x) + xoff;
    float4*       __restrict__ op = reinterpret_cast<float4*>(out)     + xoff;
    const unsigned* __restrict__ pm = &g_pm[b][0];
    const int fbase = seg * 1024;
    const int shift = (threadIdx.x & 7) * 4;

    // front-batch the 4 x loads (independent of all predecessors)
    float4 xv[4];
    #pragma unroll
    for (int k = 0; k < 4; k++)
        xv[k] = __ldcs(&xp[threadIdx.x + (k << 8)]);

#if __CUDA_ARCH__ >= 900
    cudaGridDependencySynchronize();    // finalize (and transitively all) done
#endif

    const float2 sb = g_sb[p];
    const float scale = sb.x;
    const float bias  = sb.y;

    #pragma unroll
    for (int k = 0; k < 4; k++) {
        const int i = threadIdx.x + (k << 8);
        unsigned nib = (pm[(fbase + i) >> 3] >> shift) & 0xFu;

        float4 ov;
        ov.x = (nib & 1u) ? xv[k].x : fmaf(xv[k].x, scale, bias);
        ov.y = (nib & 2u) ? xv[k].y : fmaf(xv[k].y, scale, bias);
        ov.z = (nib & 4u) ? xv[k].z : fmaf(xv[k].z, scale, bias);
        ov.w = (nib & 8u) ? xv[k].w : fmaf(xv[k].w, scale, bias);

        __stcs(&op[i], ov);
    }
}

// ---------------------------------------------------------------------------
// Host: PDL launches (ProgrammaticStreamSerialization on dependent kernels)
// ---------------------------------------------------------------------------
template <typename K, typename... Args>
static void launch_pdl(K kernel, dim3 grid, dim3 block, Args... args)
{
    cudaLaunchConfig_t cfg = {};
    cfg.gridDim  = grid;
    cfg.blockDim = block;
    cfg.stream   = 0;
    cudaLaunchAttribute attr[1];
    attr[0].id = cudaLaunchAttributeProgrammaticStreamSerialization;
    attr[0].val.programmaticStreamSerializationAllowed = 1;
    cfg.attrs    = attr;
    cfg.numAttrs = 1;
    cudaLaunchKernelEx(&cfg, kernel, args...);
}

extern "C" void kernel_launch(void* const* d_in, const int* in_sizes, int n_in,
                              void* d_out, int out_size)
{
    const float* x    = (const float*)d_in[0];
    const float* mask = (const float*)d_in[1];
    float* out        = (float*)d_out;

    pack_kernel<<<128, 256>>>(mask);
    launch_pdl(stats_kernel,    dim3(4 * NBC), dim3(512), x);
    launch_pdl(finalize_kernel, dim3(4),       dim3(256));
    launch_pdl(apply_kernel,    dim3(16 * NBC), dim3(256), x, out);
}

// round 15
// speedup vs baseline: 1.1657x; 1.0013x over previous
#include <cuda_runtime.h>
#include <math.h>

// MaskedLightAdaIN, four-launch PDL pipeline:
//   0) pack_kernel:     mask f32 -> 1 bit/pixel (128 KB)
//   1) stats_kernel:    per quarter-plane partials, 8-deep front-batched x
//                       loads BEFORE griddepsync (overlap with pack tail)
//   2) finalize_kernel: combine 4 slots/plane -> scale/bias (deterministic)
//   3) apply_kernel:    front-batched x loads before griddepsync (overlap with
//                       stats/finalize tails), then blend + streaming stores
// All dependent launches use ProgrammaticStreamSerialization; every read of
// predecessor-written data happens after cudaGridDependencySynchronize().

#define NB      16
#define NBC     1024            // planes (B*C)
#define HW      65536
#define HW4     16384           // float4 per plane
#define Q4      4096            // float4 per quarter plane
#define PMW     2048            // packed-mask words per batch (HW/32)
#define EPSV    1e-8f

__device__ unsigned g_pm[NB][PMW];    // 1 bit per pixel
__device__ float    g_part[NBC][4][5];
__device__ float2   g_sb[NBC];

// ---------------------------------------------------------------------------
// Pass 0: bit-pack the mask. One thread per uint32 word (32 pixels).
// ---------------------------------------------------------------------------
__global__ void __launch_bounds__(256) pack_kernel(const float* __restrict__ mask)
{
    const int w  = blockIdx.x * 256 + threadIdx.x;   // 0..32767
    const int b  = w >> 11;
    const int wi = w & (PMW - 1);

    const float4* __restrict__ mp = reinterpret_cast<const float4*>(mask)
                                  + (size_t)b * HW4 + wi * 8;
    unsigned bits = 0;
    #pragma unroll
    for (int k = 0; k < 8; k++) {
        float4 mv = __ldcs(&mp[k]);
        unsigned nib = (mv.x >= 0.5f) | ((mv.y >= 0.5f) << 1)
                     | ((mv.z >= 0.5f) << 2) | ((mv.w >= 0.5f) << 3);
        bits |= nib << (4 * k);
    }
    g_pm[b][wi] = bits;
}

// ---------------------------------------------------------------------------
// Pass 1: partial sums per quarter-plane. 512 threads x 8 float4, all loads
// of x front-batched BEFORE the dependency sync (x doesn't depend on pack).
// ---------------------------------------------------------------------------
__global__ void __launch_bounds__(512) stats_kernel(const float* __restrict__ x)
{
    const int blk = blockIdx.x;         // 0..4095
    const int p   = blk >> 2;           // plane
    const int q   = blk & 3;            // quarter
    const int b   = p >> 6;             // batch

    const float4* __restrict__ xp = reinterpret_cast<const float4*>(x)
                                  + (size_t)p * HW4 + q * Q4;
    const unsigned* __restrict__ pm = &g_pm[b][0];
    const int fbase = q * Q4;
    const int shift = (threadIdx.x & 7) * 4;   // stride 512 == 0 mod 8

    // front-batch: 8 independent LDG.128 of x
    float4 r[8];
    #pragma unroll
    for (int k = 0; k < 8; k++)
        r[k] = __ldcs(&xp[threadIdx.x + (k << 9)]);

#if __CUDA_ARCH__ >= 900
    cudaGridDependencySynchronize();    // pack's g_pm now visible
#endif

    unsigned w[8];
    #pragma unroll
    for (int k = 0; k < 8; k++)
        w[k] = pm[(fbase + threadIdx.x + (k << 9)) >> 3];

    float s_all = 0.f, q_all = 0.f, s_fg = 0.f, q_fg = 0.f;
    int   n_cnt = 0;

    #pragma unroll
    for (int k = 0; k < 8; k++) {
        unsigned nib = (w[k] >> shift) & 0xFu;
        float x0 = r[k].x, x1 = r[k].y, x2 = r[k].z, x3 = r[k].w;
        float q0 = x0*x0, q1 = x1*x1, q2 = x2*x2, q3 = x3*x3;

        s_all += x0 + x1 + x2 + x3;
        q_all += q0 + q1 + q2 + q3;
        if (nib & 1u) { s_fg += x0; q_fg += q0; }
        if (nib & 2u) { s_fg += x1; q_fg += q1; }
        if (nib & 4u) { s_fg += x2; q_fg += q2; }
        if (nib & 8u) { s_fg += x3; q_fg += q3; }
        n_cnt += __popc(nib);
    }
    float n_fg = (float)n_cnt;

    #pragma unroll
    for (int o = 16; o > 0; o >>= 1) {
        s_all += __shfl_xor_sync(0xffffffffu, s_all, o);
        q_all += __shfl_xor_sync(0xffffffffu, q_all, o);
        s_fg  += __shfl_xor_sync(0xffffffffu, s_fg,  o);
        q_fg  += __shfl_xor_sync(0xffffffffu, q_fg,  o);
        n_fg  += __shfl_xor_sync(0xffffffffu, n_fg,  o);
    }

    __shared__ float red[16][5];
    const int warp = threadIdx.x >> 5;
    const int lane = threadIdx.x & 31;
    if (lane == 0) {
        red[warp][0] = s_all; red[warp][1] = q_all;
        red[warp][2] = s_fg;  red[warp][3] = q_fg;
        red[warp][4] = n_fg;
    }
    __syncthreads();

    if (threadIdx.x < 32) {
        float v0 = (lane < 16) ? red[lane][0] : 0.f;
        float v1 = (lane < 16) ? red[lane][1] : 0.f;
        float v2 = (lane < 16) ? red[lane][2] : 0.f;
        float v3 = (lane < 16) ? red[lane][3] : 0.f;
        float v4 = (lane < 16) ? red[lane][4] : 0.f;
        #pragma unroll
        for (int o = 8; o > 0; o >>= 1) {
            v0 += __shfl_xor_sync(0xffffffffu, v0, o);
            v1 += __shfl_xor_sync(0xffffffffu, v1, o);
            v2 += __shfl_xor_sync(0xffffffffu, v2, o);
            v3 += __shfl_xor_sync(0xffffffffu, v3, o);
            v4 += __shfl_xor_sync(0xffffffffu, v4, o);
        }
        if (lane == 0) {
            g_part[p][q][0] = v0;
            g_part[p][q][1] = v1;
            g_part[p][q][2] = v2;
            g_part[p][q][3] = v3;
            g_part[p][q][4] = v4;
        }
    }
}

// ---------------------------------------------------------------------------
// Pass 2: combine quarter slots (fixed order -> bit-deterministic)
// ---------------------------------------------------------------------------
__global__ void finalize_kernel()
{
#if __CUDA_ARCH__ >= 900
    cudaGridDependencySynchronize();    // stats' g_part now visible
#endif
    const int p = blockIdx.x * blockDim.x + threadIdx.x;
    if (p >= NBC) return;

    float t0 = 0.f, t1 = 0.f, t2 = 0.f, t3 = 0.f, nf = 0.f;
    #pragma unroll
    for (int s = 0; s < 4; s++) {
        t0 += g_part[p][s][0];
        t1 += g_part[p][s][1];
        t2 += g_part[p][s][2];
        t3 += g_part[p][s][3];
        nf += g_part[p][s][4];
    }
    float nb  = (float)HW - nf;
    float s_b = t0 - t2, q_b = t1 - t3;

    float mu_f  = t2 / nf;
    float var_f = fmaxf(t3 - t2 * mu_f, 0.f) / (nf - 1.f);
    float sig_f = sqrtf(var_f);

    float mu_b  = s_b / nb;
    float var_b = fmaxf(q_b - s_b * mu_b, 0.f) / (nb - 1.f);
    float sig_b = sqrtf(var_b);

    float scale = sig_f / (sig_b + EPSV);
    float bias  = mu_f - mu_b * scale;
    g_sb[p] = make_float2(scale, bias);
}

// ---------------------------------------------------------------------------
// Pass 3: apply. x loads front-batched BEFORE the dependency sync; everything
// written by predecessors (g_pm, g_sb) is read after it. Reversed block order
// keeps the weak L2-tail reuse from R12.
// ---------------------------------------------------------------------------
__global__ void __launch_bounds__(256) apply_kernel(const float* __restrict__ x,
                                                    float* __restrict__ out)
{
    const int blk = (16 * NBC - 1) - blockIdx.x;
    const int p   = blk >> 4;           // plane
    const int seg = blk & 15;           // 1024-float4 segment
    const int b   = p >> 6;

    const size_t xoff = (size_t)p * HW4 + (size_t)seg * 1024;
    const float4* __restrict__ xp = reinterpret_cast<const float4*>(x) + xoff;
    float4*       __restrict__ op = reinterpret_cast<float4*>(out)     + xoff;
    const unsigned* __restrict__ pm = &g_pm[b][0];
    const int fbase = seg * 1024;
    const int shift = (threadIdx.x & 7) * 4;

    // front-batch the 4 x loads (independent of all predecessors)
    float4 xv[4];
    #pragma unroll
    for (int k = 0; k < 4; k++)
        xv[k] = __ldcs(&xp[threadIdx.x + (k << 8)]);

#if __CUDA_ARCH__ >= 900
    cudaGridDependencySynchronize();    // finalize (and transitively all) done
#endif

    const float2 sb = g_sb[p];
    const float scale = sb.x;
    const float bias  = sb.y;

    #pragma unroll
    for (int k = 0; k < 4; k++) {
        const int i = threadIdx.x + (k << 8);
        unsigned nib = (pm[(fbase + i) >> 3] >> shift) & 0xFu;

        float4 ov;
        ov.x = (nib & 1u) ? xv[k].x : fmaf(xv[k].x, scale, bias);
        ov.y = (nib & 2u) ? xv[k].y : fmaf(xv[k].y, scale, bias);
        ov.z = (nib & 4u) ? xv[k].z : fmaf(xv[k].z, scale, bias);
        ov.w = (nib & 8u) ? xv[k].w : fmaf(xv[k].w, scale, bias);

        __stcs(&op[i], ov);
    }
}

// ---------------------------------------------------------------------------
// Host: PDL launches (ProgrammaticStreamSerialization on dependent kernels)
// ---------------------------------------------------------------------------
template <typename K, typename... Args>
static void launch_pdl(K kernel, dim3 grid, dim3 block, Args... args)
{
    cudaLaunchConfig_t cfg = {};
    cfg.gridDim  = grid;
    cfg.blockDim = block;
    cfg.stream   = 0;
    cudaLaunchAttribute attr[1];
    attr[0].id = cudaLaunchAttributeProgrammaticStreamSerialization;
    attr[0].val.programmaticStreamSerializationAllowed = 1;
    cfg.attrs    = attr;
    cfg.numAttrs = 1;
    cudaLaunchKernelEx(&cfg, kernel, args...);
}

extern "C" void kernel_launch(void* const* d_in, const int* in_sizes, int n_in,
                              void* d_out, int out_size)
{
    const float* x    = (const float*)d_in[0];
    const float* mask = (const float*)d_in[1];
    float* out        = (float*)d_out;

    pack_kernel<<<128, 256>>>(mask);
    launch_pdl(stats_kernel,    dim3(4 * NBC), dim3(512), x);
    launch_pdl(finalize_kernel, dim3(4),       dim3(256));
    launch_pdl(apply_kernel,    dim3(16 * NBC), dim3(256), x, out);
}

// round 16
// speedup vs baseline: 1.1663x; 1.0005x over previous
#include <cuda_runtime.h>
#include <math.h>

// MaskedLightAdaIN, four-launch PDL pipeline:
//   0) pack_kernel:     mask f32 -> 1 bit/pixel (128 KB)
//   1) stats_kernel:    per quarter-plane partials, 8-deep front-batched x
//                       loads BEFORE griddepsync (overlap with pack tail)
//   2) finalize_kernel: combine 4 slots/plane -> scale/bias (deterministic)
//   3) apply_kernel:    front-batched x loads before griddepsync (overlap with
//                       stats/finalize tails), then blend + streaming stores
// All dependent launches use ProgrammaticStreamSerialization; every read of
// predecessor-written data happens after cudaGridDependencySynchronize().

#define NB      16
#define NBC     1024            // planes (B*C)
#define HW      65536
#define HW4     16384           // float4 per plane
#define Q4      4096            // float4 per quarter plane
#define PMW     2048            // packed-mask words per batch (HW/32)
#define EPSV    1e-8f

__device__ unsigned g_pm[NB][PMW];    // 1 bit per pixel
__device__ float    g_part[NBC][4][5];
__device__ float2   g_sb[NBC];

// ---------------------------------------------------------------------------
// Pass 0: bit-pack the mask. One thread per uint32 word (32 pixels).
// ---------------------------------------------------------------------------
__global__ void __launch_bounds__(256) pack_kernel(const float* __restrict__ mask)
{
    const int w  = blockIdx.x * 256 + threadIdx.x;   // 0..32767
    const int b  = w >> 11;
    const int wi = w & (PMW - 1);

    const float4* __restrict__ mp = reinterpret_cast<const float4*>(mask)
                                  + (size_t)b * HW4 + wi * 8;
    unsigned bits = 0;
    #pragma unroll
    for (int k = 0; k < 8; k++) {
        float4 mv = __ldcs(&mp[k]);
        unsigned nib = (mv.x >= 0.5f) | ((mv.y >= 0.5f) << 1)
                     | ((mv.z >= 0.5f) << 2) | ((mv.w >= 0.5f) << 3);
        bits |= nib << (4 * k);
    }
    g_pm[b][wi] = bits;
}

// ---------------------------------------------------------------------------
// Pass 1: partial sums per quarter-plane. 512 threads x 8 float4, all loads
// of x front-batched BEFORE the dependency sync (x doesn't depend on pack).
// ---------------------------------------------------------------------------
__global__ void __launch_bounds__(512) stats_kernel(const float* __restrict__ x)
{
    const int blk = blockIdx.x;         // 0..4095
    const int p   = blk >> 2;           // plane
    const int q   = blk & 3;            // quarter
    const int b   = p >> 6;             // batch

    const float4* __restrict__ xp = reinterpret_cast<const float4*>(x)
                                  + (size_t)p * HW4 + q * Q4;
    const unsigned* __restrict__ pm = &g_pm[b][0];
    const int fbase = q * Q4;
    const int shift = (threadIdx.x & 7) * 4;   // stride 512 == 0 mod 8

    // front-batch: 8 independent LDG.128 of x
    float4 r[8];
    #pragma unroll
    for (int k = 0; k < 8; k++)
        r[k] = __ldcs(&xp[threadIdx.x + (k << 9)]);

#if __CUDA_ARCH__ >= 900
    cudaGridDependencySynchronize();    // pack's g_pm now visible
#endif

    unsigned w[8];
    #pragma unroll
    for (int k = 0; k < 8; k++)
        w[k] = pm[(fbase + threadIdx.x + (k << 9)) >> 3];

    float s_all = 0.f, q_all = 0.f, s_fg = 0.f, q_fg = 0.f;
    int   n_cnt = 0;

    #pragma unroll
    for (int k = 0; k < 8; k++) {
        unsigned nib = (w[k] >> shift) & 0xFu;
        float x0 = r[k].x, x1 = r[k].y, x2 = r[k].z, x3 = r[k].w;
        float q0 = x0*x0, q1 = x1*x1, q2 = x2*x2, q3 = x3*x3;

        s_all += x0 + x1 + x2 + x3;
        q_all += q0 + q1 + q2 + q3;
        if (nib & 1u) { s_fg += x0; q_fg += q0; }
        if (nib & 2u) { s_fg += x1; q_fg += q1; }
        if (nib & 4u) { s_fg += x2; q_fg += q2; }
        if (nib & 8u) { s_fg += x3; q_fg += q3; }
        n_cnt += __popc(nib);
    }
    float n_fg = (float)n_cnt;

    #pragma unroll
    for (int o = 16; o > 0; o >>= 1) {
        s_all += __shfl_xor_sync(0xffffffffu, s_all, o);
        q_all += __shfl_xor_sync(0xffffffffu, q_all, o);
        s_fg  += __shfl_xor_sync(0xffffffffu, s_fg,  o);
        q_fg  += __shfl_xor_sync(0xffffffffu, q_fg,  o);
        n_fg  += __shfl_xor_sync(0xffffffffu, n_fg,  o);
    }

    __shared__ float red[16][5];
    const int warp = threadIdx.x >> 5;
    const int lane = threadIdx.x & 31;
    if (lane == 0) {
        red[warp][0] = s_all; red[warp][1] = q_all;
        red[warp][2] = s_fg;  red[warp][3] = q_fg;
        red[warp][4] = n_fg;
    }
    __syncthreads();

    if (threadIdx.x < 32) {
        float v0 = (lane < 16) ? red[lane][0] : 0.f;
        float v1 = (lane < 16) ? red[lane][1] : 0.f;
        float v2 = (lane < 16) ? red[lane][2] : 0.f;
        float v3 = (lane < 16) ? red[lane][3] : 0.f;
        float v4 = (lane < 16) ? red[lane][4] : 0.f;
        #pragma unroll
        for (int o = 8; o > 0; o >>= 1) {
            v0 += __shfl_xor_sync(0xffffffffu, v0, o);
            v1 += __shfl_xor_sync(0xffffffffu, v1, o);
            v2 += __shfl_xor_sync(0xffffffffu, v2, o);
            v3 += __shfl_xor_sync(0xffffffffu, v3, o);
            v4 += __shfl_xor_sync(0xffffffffu, v4, o);
        }
        if (lane == 0) {
            g_part[p][q][0] = v0;
            g_part[p][q][1] = v1;
            g_part[p][q][2] = v2;
            g_part[p][q][3] = v3;
            g_part[p][q][4] = v4;
        }
    }
}

// ---------------------------------------------------------------------------
// Pass 2: combine quarter slots (fixed order -> bit-deterministic)
// ---------------------------------------------------------------------------
__global__ void finalize_kernel()
{
#if __CUDA_ARCH__ >= 900
    cudaGridDependencySynchronize();    // stats' g_part now visible
#endif
    const int p = blockIdx.x * blockDim.x + threadIdx.x;
    if (p >= NBC) return;

    float t0 = 0.f, t1 = 0.f, t2 = 0.f, t3 = 0.f, nf = 0.f;
    #pragma unroll
    for (int s = 0; s < 4; s++) {
        t0 += g_part[p][s][0];
        t1 += g_part[p][s][1];
        t2 += g_part[p][s][2];
        t3 += g_part[p][s][3];
        nf += g_part[p][s][4];
    }
    float nb  = (float)HW - nf;
    float s_b = t0 - t2, q_b = t1 - t3;

    float mu_f  = t2 / nf;
    float var_f = fmaxf(t3 - t2 * mu_f, 0.f) / (nf - 1.f);
    float sig_f = sqrtf(var_f);

    float mu_b  = s_b / nb;
    float var_b = fmaxf(q_b - s_b * mu_b, 0.f) / (nb - 1.f);
    float sig_b = sqrtf(var_b);

    float scale = sig_f / (sig_b + EPSV);
    float bias  = mu_f - mu_b * scale;
    g_sb[p] = make_float2(scale, bias);
}

// ---------------------------------------------------------------------------
// Pass 3: apply. x loads front-batched BEFORE the dependency sync; everything
// written by predecessors (g_pm, g_sb) is read after it. Reversed block order
// keeps the weak L2-tail reuse from R12.
// ---------------------------------------------------------------------------
__global__ void __launch_bounds__(256) apply_kernel(const float* __restrict__ x,
                                                    float* __restrict__ out)
{
    const int blk = (16 * NBC - 1) - blockIdx.x;
    const int p   = blk >> 4;           // plane
    const int seg = blk & 15;           // 1024-float4 segment
    const int b   = p >> 6;

    const size_t xoff = (size_t)p * HW4 + (size_t)seg * 1024;
    const float4* __restrict__ xp = reinterpret_cast<const float4*>(x) + xoff;
    float4*       __restrict__ op = reinterpret_cast<float4*>(out)     + xoff;
    const unsigned* __restrict__ pm = &g_pm[b][0];
    const int fbase = seg * 1024;
    const int shift = (threadIdx.x & 7) * 4;

    // front-batch the 4 x loads (independent of all predecessors)
    float4 xv[4];
    #pragma unroll
    for (int k = 0; k < 4; k++)
        xv[k] = __ldcs(&xp[threadIdx.x + (k << 8)]);

#if __CUDA_ARCH__ >= 900
    cudaGridDependencySynchronize();    // finalize (and transitively all) done
#endif

    const float2 sb = g_sb[p];
    const float scale = sb.x;
    const float bias  = sb.y;

    #pragma unroll
    for (int k = 0; k < 4; k++) {
        const int i = threadIdx.x + (k << 8);
        unsigned nib = (pm[(fbase + i) >> 3] >> shift) & 0xFu;

        float4 ov;
        ov.x = (nib & 1u) ? xv[k].x : fmaf(xv[k].x, scale, bias);
        ov.y = (nib & 2u) ? xv[k].y : fmaf(xv[k].y, scale, bias);
        ov.z = (nib & 4u) ? xv[k].z : fmaf(xv[k].z, scale, bias);
        ov.w = (nib & 8u) ? xv[k].w : fmaf(xv[k].w, scale, bias);

        __stcs(&op[i], ov);
    }
}

// ---------------------------------------------------------------------------
// Host: PDL launches (ProgrammaticStreamSerialization on dependent kernels)
// ---------------------------------------------------------------------------
template <typename K, typename... Args>
static void launch_pdl(K kernel, dim3 grid, dim3 block, Args... args)
{
    cudaLaunchConfig_t cfg = {};
    cfg.gridDim  = grid;
    cfg.blockDim = block;
    cfg.stream   = 0;
    cudaLaunchAttribute attr[1];
    attr[0].id = cudaLaunchAttributeProgrammaticStreamSerialization;
    attr[0].val.programmaticStreamSerializationAllowed = 1;
    cfg.attrs    = attr;
    cfg.numAttrs = 1;
    cudaLaunchKernelEx(&cfg, kernel, args...);
}

extern "C" void kernel_launch(void* const* d_in, const int* in_sizes, int n_in,
                              void* d_out, int out_size)
{
    const float* x    = (const float*)d_in[0];
    const float* mask = (const float*)d_in[1];
    float* out        = (float*)d_out;

    pack_kernel<<<128, 256>>>(mask);
    launch_pdl(stats_kernel,    dim3(4 * NBC), dim3(512), x);
    launch_pdl(finalize_kernel, dim3(4),       dim3(256));
    launch_pdl(apply_kernel,    dim3(16 * NBC), dim3(256), x, out);
}

// round 17
// speedup vs baseline: 1.1675x; 1.0010x over previous
#include <cuda_runtime.h>
#include <math.h>

// MaskedLightAdaIN, four-launch PDL pipeline:
//   0) pack_kernel:     mask f32 -> 1 bit/pixel (128 KB)
//   1) stats_kernel:    per quarter-plane partials, 8-deep front-batched x
//                       loads BEFORE griddepsync (overlap with pack tail)
//   2) finalize_kernel: combine 4 slots/plane -> scale/bias (deterministic)
//   3) apply_kernel:    front-batched x loads before griddepsync (overlap with
//                       stats/finalize tails), then blend + streaming stores
// All dependent launches use ProgrammaticStreamSerialization; every read of
// predecessor-written data happens after cudaGridDependencySynchronize().

#define NB      16
#define NBC     1024            // planes (B*C)
#define HW      65536
#define HW4     16384           // float4 per plane
#define Q4      4096            // float4 per quarter plane
#define PMW     2048            // packed-mask words per batch (HW/32)
#define EPSV    1e-8f

__device__ unsigned g_pm[NB][PMW];    // 1 bit per pixel
__device__ float    g_part[NBC][4][5];
__device__ float2   g_sb[NBC];

// ---------------------------------------------------------------------------
// Pass 0: bit-pack the mask. One thread per uint32 word (32 pixels).
// ---------------------------------------------------------------------------
__global__ void __launch_bounds__(256) pack_kernel(const float* __restrict__ mask)
{
    const int w  = blockIdx.x * 256 + threadIdx.x;   // 0..32767
    const int b  = w >> 11;
    const int wi = w & (PMW - 1);

    const float4* __restrict__ mp = reinterpret_cast<const float4*>(mask)
                                  + (size_t)b * HW4 + wi * 8;
    unsigned bits = 0;
    #pragma unroll
    for (int k = 0; k < 8; k++) {
        float4 mv = __ldcs(&mp[k]);
        unsigned nib = (mv.x >= 0.5f) | ((mv.y >= 0.5f) << 1)
                     | ((mv.z >= 0.5f) << 2) | ((mv.w >= 0.5f) << 3);
        bits |= nib << (4 * k);
    }
    g_pm[b][wi] = bits;
}

// ---------------------------------------------------------------------------
// Pass 1: partial sums per quarter-plane. 512 threads x 8 float4, all loads
// of x front-batched BEFORE the dependency sync (x doesn't depend on pack).
// ---------------------------------------------------------------------------
__global__ void __launch_bounds__(512) stats_kernel(const float* __restrict__ x)
{
    const int blk = blockIdx.x;         // 0..4095
    const int p   = blk >> 2;           // plane
    const int q   = blk & 3;            // quarter
    const int b   = p >> 6;             // batch

    const float4* __restrict__ xp = reinterpret_cast<const float4*>(x)
                                  + (size_t)p * HW4 + q * Q4;
    const unsigned* __restrict__ pm = &g_pm[b][0];
    const int fbase = q * Q4;
    const int shift = (threadIdx.x & 7) * 4;   // stride 512 == 0 mod 8

    // front-batch: 8 independent LDG.128 of x
    float4 r[8];
    #pragma unroll
    for (int k = 0; k < 8; k++)
        r[k] = __ldcs(&xp[threadIdx.x + (k << 9)]);

#if __CUDA_ARCH__ >= 900
    cudaGridDependencySynchronize();    // pack's g_pm now visible
#endif

    unsigned w[8];
    #pragma unroll
    for (int k = 0; k < 8; k++)
        w[k] = pm[(fbase + threadIdx.x + (k << 9)) >> 3];

    float s_all = 0.f, q_all = 0.f, s_fg = 0.f, q_fg = 0.f;
    int   n_cnt = 0;

    #pragma unroll
    for (int k = 0; k < 8; k++) {
        unsigned nib = (w[k] >> shift) & 0xFu;
        float x0 = r[k].x, x1 = r[k].y, x2 = r[k].z, x3 = r[k].w;
        float q0 = x0*x0, q1 = x1*x1, q2 = x2*x2, q3 = x3*x3;

        s_all += x0 + x1 + x2 + x3;
        q_all += q0 + q1 + q2 + q3;
        if (nib & 1u) { s_fg += x0; q_fg += q0; }
        if (nib & 2u) { s_fg += x1; q_fg += q1; }
        if (nib & 4u) { s_fg += x2; q_fg += q2; }
        if (nib & 8u) { s_fg += x3; q_fg += q3; }
        n_cnt += __popc(nib);
    }
    float n_fg = (float)n_cnt;

    #pragma unroll
    for (int o = 16; o > 0; o >>= 1) {
        s_all += __shfl_xor_sync(0xffffffffu, s_all, o);
        q_all += __shfl_xor_sync(0xffffffffu, q_all, o);
        s_fg  += __shfl_xor_sync(0xffffffffu, s_fg,  o);
        q_fg  += __shfl_xor_sync(0xffffffffu, q_fg,  o);
        n_fg  += __shfl_xor_sync(0xffffffffu, n_fg,  o);
    }

    __shared__ float red[16][5];
    const int warp = threadIdx.x >> 5;
    const int lane = threadIdx.x & 31;
    if (lane == 0) {
        red[warp][0] = s_all; red[warp][1] = q_all;
        red[warp][2] = s_fg;  red[warp][3] = q_fg;
        red[warp][4] = n_fg;
    }
    __syncthreads();

    if (threadIdx.x < 32) {
        float v0 = (lane < 16) ? red[lane][0] : 0.f;
        float v1 = (lane < 16) ? red[lane][1] : 0.f;
        float v2 = (lane < 16) ? red[lane][2] : 0.f;
        float v3 = (lane < 16) ? red[lane][3] : 0.f;
        float v4 = (lane < 16) ? red[lane][4] : 0.f;
        #pragma unroll
        for (int o = 8; o > 0; o >>= 1) {
            v0 += __shfl_xor_sync(0xffffffffu, v0, o);
            v1 += __shfl_xor_sync(0xffffffffu, v1, o);
            v2 += __shfl_xor_sync(0xffffffffu, v2, o);
            v3 += __shfl_xor_sync(0xffffffffu, v3, o);
            v4 += __shfl_xor_sync(0xffffffffu, v4, o);
        }
        if (lane == 0) {
            g_part[p][q][0] = v0;
            g_part[p][q][1] = v1;
            g_part[p][q][2] = v2;
            g_part[p][q][3] = v3;
            g_part[p][q][4] = v4;
        }
    }
}

// ---------------------------------------------------------------------------
// Pass 2: combine quarter slots (fixed order -> bit-deterministic)
// ---------------------------------------------------------------------------
__global__ void finalize_kernel()
{
#if __CUDA_ARCH__ >= 900
    cudaGridDependencySynchronize();    // stats' g_part now visible
#endif
    const int p = blockIdx.x * blockDim.x + threadIdx.x;
    if (p >= NBC) return;

    float t0 = 0.f, t1 = 0.f, t2 = 0.f, t3 = 0.f, nf = 0.f;
    #pragma unroll
    for (int s = 0; s < 4; s++) {
        t0 += g_part[p][s][0];
        t1 += g_part[p][s][1];
        t2 += g_part[p][s][2];
        t3 += g_part[p][s][3];
        nf += g_part[p][s][4];
    }
    float nb  = (float)HW - nf;
    float s_b = t0 - t2, q_b = t1 - t3;

    float mu_f  = t2 / nf;
    float var_f = fmaxf(t3 - t2 * mu_f, 0.f) / (nf - 1.f);
    float sig_f = sqrtf(var_f);

    float mu_b  = s_b / nb;
    float var_b = fmaxf(q_b - s_b * mu_b, 0.f) / (nb - 1.f);
    float sig_b = sqrtf(var_b);

    float scale = sig_f / (sig_b + EPSV);
    float bias  = mu_f - mu_b * scale;
    g_sb[p] = make_float2(scale, bias);
}

// ---------------------------------------------------------------------------
// Pass 3: apply. x loads front-batched BEFORE the dependency sync; everything
// written by predecessors (g_pm, g_sb) is read after it. Reversed block order
// keeps the weak L2-tail reuse from R12.
// ---------------------------------------------------------------------------
__global__ void __launch_bounds__(256) apply_kernel(const float* __restrict__ x,
                                                    float* __restrict__ out)
{
    const int blk = (16 * NBC - 1) - blockIdx.x;
    const int p   = blk >> 4;           // plane
    const int seg = blk & 15;           // 1024-float4 segment
    const int b   = p >> 6;

    const size_t xoff = (size_t)p * HW4 + (size_t)seg * 1024;
    const float4* __restrict__ xp = reinterpret_cast<const float4*>(x) + xoff;
    float4*       __restrict__ op = reinterpret_cast<float4*>(out)     + xoff;
    const unsigned* __restrict__ pm = &g_pm[b][0];
    const int fbase = seg * 1024;
    const int shift = (threadIdx.x & 7) * 4;

    // front-batch the 4 x loads (independent of all predecessors)
    float4 xv[4];
    #pragma unroll
    for (int k = 0; k < 4; k++)
        xv[k] = __ldcs(&xp[threadIdx.x + (k << 8)]);

#if __CUDA_ARCH__ >= 900
    cudaGridDependencySynchronize();    // finalize (and transitively all) done
#endif

    const float2 sb = g_sb[p];
    const float scale = sb.x;
    const float bias  = sb.y;

    #pragma unroll
    for (int k = 0; k < 4; k++) {
        const int i = threadIdx.x + (k << 8);
        unsigned nib = (pm[(fbase + i) >> 3] >> shift) & 0xFu;

        float4 ov;
        ov.x = (nib & 1u) ? xv[k].x : fmaf(xv[k].x, scale, bias);
        ov.y = (nib & 2u) ? xv[k].y : fmaf(xv[k].y, scale, bias);
        ov.z = (nib & 4u) ? xv[k].z : fmaf(xv[k].z, scale, bias);
        ov.w = (nib & 8u) ? xv[k].w : fmaf(xv[k].w, scale, bias);

        __stcs(&op[i], ov);
    }
}

// ---------------------------------------------------------------------------
// Host: PDL launches (ProgrammaticStreamSerialization on dependent kernels)
// ---------------------------------------------------------------------------
template <typename K, typename... Args>
static void launch_pdl(K kernel, dim3 grid, dim3 block, Args... args)
{
    cudaLaunchConfig_t cfg = {};
    cfg.gridDim  = grid;
    cfg.blockDim = block;
    cfg.stream   = 0;
    cudaLaunchAttribute attr[1];
    attr[0].id = cudaLaunchAttributeProgrammaticStreamSerialization;
    attr[0].val.programmaticStreamSerializationAllowed = 1;
    cfg.attrs    = attr;
    cfg.numAttrs = 1;
    cudaLaunchKernelEx(&cfg, kernel, args...);
}

extern "C" void kernel_launch(void* const* d_in, const int* in_sizes, int n_in,
                              void* d_out, int out_size)
{
    const float* x    = (const float*)d_in[0];
    const float* mask = (const float*)d_in[1];
    float* out        = (float*)d_out;

    pack_kernel<<<128, 256>>>(mask);
    launch_pdl(stats_kernel,    dim3(4 * NBC), dim3(512), x);
    launch_pdl(finalize_kernel, dim3(4),       dim3(256));
    launch_pdl(apply_kernel,    dim3(16 * NBC), dim3(256), x, out);
}